// round 1
// baseline (speedup 1.0000x reference)
#include <cuda_runtime.h>

#define GRID1  2048
#define BLOCK1 256

// Per-block partials: [block][0..3]=sum_d2 per bin, [4..7]=sum_abs2, [8..11]=count
__device__ float g_partials[GRID1 * 12];

__device__ __forceinline__ float fast_abs2d(float a, float b) {
    // sqrt(a*a+b*b) via rsqrt; clamp avoids rsqrt(0)->inf*0=NaN.
    float s = fmaxf(a * a + b * b, 1e-30f);
    return s * rsqrtf(s);
}

__global__ __launch_bounds__(BLOCK1)
void radial_pass1(const float4* __restrict__ x4,
                  const float4* __restrict__ y4,
                  const float4* __restrict__ d4,
                  int nvec,
                  const float* __restrict__ x,
                  const float* __restrict__ y,
                  const float* __restrict__ dist,
                  int n)
{
    float sd2[4] = {0.f, 0.f, 0.f, 0.f};
    float sa2[4] = {0.f, 0.f, 0.f, 0.f};
    int   cnt[4] = {0, 0, 0, 0};

    const int stride = gridDim.x * blockDim.x;
    for (int i = blockIdx.x * blockDim.x + threadIdx.x; i < nvec; i += stride) {
        float4 dd = d4[i];
        float4 xa = x4[2 * i + 0];
        float4 xb = x4[2 * i + 1];
        float4 ya = y4[2 * i + 0];
        float4 yb = y4[2 * i + 1];

        float ds[4] = {dd.x, dd.y, dd.z, dd.w};
        float e0[4] = {xa.x, xa.z, xb.x, xb.z};
        float e1[4] = {xa.y, xa.w, xb.y, xb.w};
        float f0[4] = {ya.x, ya.z, yb.x, yb.z};
        float f1[4] = {ya.y, ya.w, yb.y, yb.w};

        #pragma unroll
        for (int e = 0; e < 4; e++) {
            float u  = e0[e] - f0[e];
            float v  = e1[e] - f1[e];
            float d2 = u * u + v * v;
            float ad = fast_abs2d(e0[e], e1[e]) - fast_abs2d(f0[e], f1[e]);
            float a2 = ad * ad;
            int ib = (int)(ds[e] * 4.0f);
            ib = ib > 3 ? 3 : ib;
            #pragma unroll
            for (int b = 0; b < 4; b++) {
                if (b == ib) { sd2[b] += d2; sa2[b] += a2; cnt[b]++; }
            }
        }
    }

    // Scalar tail (n % 4 != 0) — no-op for this problem size, kept for safety.
    if (blockIdx.x == 0 && threadIdx.x == 0) {
        for (int j = nvec * 4; j < n; j++) {
            float u  = x[2 * j + 0] - y[2 * j + 0];
            float v  = x[2 * j + 1] - y[2 * j + 1];
            float d2 = u * u + v * v;
            float ad = fast_abs2d(x[2 * j], x[2 * j + 1]) -
                       fast_abs2d(y[2 * j], y[2 * j + 1]);
            float a2 = ad * ad;
            int ib = (int)(dist[j] * 4.0f);
            ib = ib > 3 ? 3 : ib;
            sd2[ib] += d2; sa2[ib] += a2; cnt[ib]++;
        }
    }

    // Pack 12 values and block-reduce (fixed order -> deterministic).
    float v[12];
    #pragma unroll
    for (int b = 0; b < 4; b++) {
        v[b]     = sd2[b];
        v[4 + b] = sa2[b];
        v[8 + b] = (float)cnt[b];
    }

    __shared__ float sh[BLOCK1 / 32][12];
    const int lane = threadIdx.x & 31;
    const int wid  = threadIdx.x >> 5;

    #pragma unroll
    for (int k = 0; k < 12; k++) {
        #pragma unroll
        for (int o = 16; o > 0; o >>= 1)
            v[k] += __shfl_down_sync(0xffffffffu, v[k], o);
    }
    if (lane == 0) {
        #pragma unroll
        for (int k = 0; k < 12; k++) sh[wid][k] = v[k];
    }
    __syncthreads();
    if (threadIdx.x < 12) {
        float s = 0.f;
        #pragma unroll
        for (int w = 0; w < BLOCK1 / 32; w++) s += sh[w][threadIdx.x];
        g_partials[blockIdx.x * 12 + threadIdx.x] = s;
    }
}

__global__ __launch_bounds__(BLOCK1)
void radial_pass2(float* __restrict__ out)
{
    float v[12];
    #pragma unroll
    for (int k = 0; k < 12; k++) v[k] = 0.f;

    for (int r = threadIdx.x; r < GRID1; r += blockDim.x) {
        #pragma unroll
        for (int k = 0; k < 12; k++) v[k] += g_partials[r * 12 + k];
    }

    __shared__ float sh[BLOCK1 / 32][12];
    const int lane = threadIdx.x & 31;
    const int wid  = threadIdx.x >> 5;

    #pragma unroll
    for (int k = 0; k < 12; k++) {
        #pragma unroll
        for (int o = 16; o > 0; o >>= 1)
            v[k] += __shfl_down_sync(0xffffffffu, v[k], o);
    }
    if (lane == 0) {
        #pragma unroll
        for (int k = 0; k < 12; k++) sh[wid][k] = v[k];
    }
    __syncthreads();

    if (threadIdx.x == 0) {
        float tot[12];
        #pragma unroll
        for (int k = 0; k < 12; k++) {
            float s = 0.f;
            #pragma unroll
            for (int w = 0; w < BLOCK1 / 32; w++) s += sh[w][k];
            tot[k] = s;
        }
        float loss = 0.f;
        #pragma unroll
        for (int b = 0; b < 4; b++) {
            float c = tot[8 + b];
            if (c > 0.f)
                loss += tot[b] / (2.0f * c) + 0.1f * tot[4 + b] / c;
        }
        out[0] = loss;
    }
}

extern "C" void kernel_launch(void* const* d_in, const int* in_sizes, int n_in,
                              void* d_out, int out_size)
{
    const float* x    = (const float*)d_in[0];   // [N,2] f32
    const float* y    = (const float*)d_in[1];   // [N,2] f32
    const float* dist = (const float*)d_in[2];   // [N]   f32
    const int n    = in_sizes[2];
    const int nvec = n >> 2;

    radial_pass1<<<GRID1, BLOCK1>>>(
        (const float4*)x, (const float4*)y, (const float4*)dist,
        nvec, x, y, dist, n);
    radial_pass2<<<1, BLOCK1>>>((float*)d_out);
}

// round 2
// speedup vs baseline: 1.0927x; 1.0927x over previous
#include <cuda_runtime.h>

#define GRID1  2048
#define BLOCK1 256

// Per-block partials: [block][0..3] = combined sum (d2 + 0.2*ad^2) per bin,
//                     [block][4..7] = count per bin (as float, exact < 2^24)
__device__ float        g_partials[GRID1 * 8];
__device__ unsigned int g_ticket;   // zero-init; last block resets to 0 each launch

__device__ __forceinline__ float fast_abs2d(float a, float b) {
    // sqrt(a*a+b*b) via rsqrt; clamp avoids rsqrt(0) -> inf*0 = NaN.
    float s = fmaxf(fmaf(a, a, b * b), 1e-30f);
    return s * rsqrtf(s);
}

__global__ __launch_bounds__(BLOCK1)
void radial_fused(const float4* __restrict__ x4,
                  const float4* __restrict__ y4,
                  const float4* __restrict__ d4,
                  int nvec,
                  const float* __restrict__ x,
                  const float* __restrict__ y,
                  const float* __restrict__ dist,
                  int n,
                  float* __restrict__ out)
{
    float sm[4] = {0.f, 0.f, 0.f, 0.f};   // combined sums per bin
    unsigned cntp = 0u;                    // 4 packed 8-bit counts

    const int stride = gridDim.x * blockDim.x;
    #pragma unroll 2
    for (int i = blockIdx.x * blockDim.x + threadIdx.x; i < nvec; i += stride) {
        float4 dd = __ldcs(d4 + i);
        float4 xa = __ldcs(x4 + 2 * i + 0);
        float4 xb = __ldcs(x4 + 2 * i + 1);
        float4 ya = __ldcs(y4 + 2 * i + 0);
        float4 yb = __ldcs(y4 + 2 * i + 1);

        float ds[4] = {dd.x, dd.y, dd.z, dd.w};
        float e0[4] = {xa.x, xa.z, xb.x, xb.z};
        float e1[4] = {xa.y, xa.w, xb.y, xb.w};
        float f0[4] = {ya.x, ya.z, yb.x, yb.z};
        float f1[4] = {ya.y, ya.w, yb.y, yb.w};

        #pragma unroll
        for (int e = 0; e < 4; e++) {
            float u  = e0[e] - f0[e];
            float v  = e1[e] - f1[e];
            float d2 = fmaf(u, u, v * v);
            float ad = fast_abs2d(e0[e], e1[e]) - fast_abs2d(f0[e], f1[e]);
            float m  = fmaf(0.2f * ad, ad, d2);   // d2 + 0.2*ad^2
            int ib = (int)(ds[e] * 4.0f);
            ib = ib > 3 ? 3 : ib;
            cntp += 1u << (ib << 3);
            #pragma unroll
            for (int b = 0; b < 4; b++)
                if (b == ib) sm[b] += m;
        }
    }

    // Scalar tail (n % 4 != 0) — no-op for this problem size, kept for safety.
    if (blockIdx.x == 0 && threadIdx.x == 0) {
        for (int j = nvec * 4; j < n; j++) {
            float u  = x[2 * j + 0] - y[2 * j + 0];
            float v  = x[2 * j + 1] - y[2 * j + 1];
            float d2 = fmaf(u, u, v * v);
            float ad = fast_abs2d(x[2 * j], x[2 * j + 1]) -
                       fast_abs2d(y[2 * j], y[2 * j + 1]);
            float m  = fmaf(0.2f * ad, ad, d2);
            int ib = (int)(dist[j] * 4.0f);
            ib = ib > 3 ? 3 : ib;
            sm[ib] += m;
            cntp += 1u << (ib << 3);
        }
    }

    // Unpack counts; block-reduce 8 values in fixed order (deterministic).
    float v[8];
    #pragma unroll
    for (int b = 0; b < 4; b++) {
        v[b]     = sm[b];
        v[4 + b] = (float)((cntp >> (b << 3)) & 0xFFu);
    }

    __shared__ float sh[BLOCK1 / 32][8];
    const int lane = threadIdx.x & 31;
    const int wid  = threadIdx.x >> 5;

    #pragma unroll
    for (int k = 0; k < 8; k++) {
        #pragma unroll
        for (int o = 16; o > 0; o >>= 1)
            v[k] += __shfl_down_sync(0xffffffffu, v[k], o);
    }
    if (lane == 0) {
        #pragma unroll
        for (int k = 0; k < 8; k++) sh[wid][k] = v[k];
    }
    __syncthreads();
    if (threadIdx.x < 8) {
        float s = 0.f;
        #pragma unroll
        for (int w = 0; w < BLOCK1 / 32; w++) s += sh[w][threadIdx.x];
        g_partials[blockIdx.x * 8 + threadIdx.x] = s;
    }

    // ---- last-block final reduction (threadfence + ticket) ----
    __shared__ int isLast;
    __threadfence();
    if (threadIdx.x == 0) {
        unsigned t = atomicAdd(&g_ticket, 1u);
        isLast = (t == (unsigned)(gridDim.x - 1));
    }
    __syncthreads();
    if (!isLast) return;

    // 256 threads: thread = (row-group r0 = tid>>3, column k = tid&7)
    const int k  = threadIdx.x & 7;
    const int r0 = threadIdx.x >> 3;
    float acc = 0.f;
    for (int r = r0; r < GRID1; r += 32)          // fixed order per thread
        acc += g_partials[r * 8 + k];

    __shared__ float sh2[256];
    __shared__ float fin[8];
    sh2[threadIdx.x] = acc;
    __syncthreads();
    if (threadIdx.x < 8) {
        float s = 0.f;
        #pragma unroll
        for (int j = 0; j < 32; j++) s += sh2[j * 8 + threadIdx.x];
        fin[threadIdx.x] = s;
    }
    __syncthreads();

    if (threadIdx.x == 0) {
        float loss = 0.f;
        #pragma unroll
        for (int b = 0; b < 4; b++) {
            float c = fin[4 + b];
            if (c > 0.f) loss += fin[b] / (2.0f * c);
        }
        out[0] = loss;
        g_ticket = 0u;   // reset for next graph replay
    }
}

extern "C" void kernel_launch(void* const* d_in, const int* in_sizes, int n_in,
                              void* d_out, int out_size)
{
    const float* x    = (const float*)d_in[0];   // [N,2] f32
    const float* y    = (const float*)d_in[1];   // [N,2] f32
    const float* dist = (const float*)d_in[2];   // [N]   f32
    const int n    = in_sizes[2];
    const int nvec = n >> 2;

    radial_fused<<<GRID1, BLOCK1>>>(
        (const float4*)x, (const float4*)y, (const float4*)dist,
        nvec, x, y, dist, n, (float*)d_out);
}

// round 3
// speedup vs baseline: 1.0960x; 1.0030x over previous
#include <cuda_runtime.h>

#define GRID1  2048
#define BLOCK1 256

// Per-block partials: [block][0..3] = combined sum (d2 + 0.2*ad^2) per bin,
//                     [block][4..7] = count per bin (as float, exact < 2^24)
__device__ float        g_partials[GRID1 * 8];
__device__ unsigned int g_ticket;   // zero-init; last block resets to 0 each launch

__global__ __launch_bounds__(BLOCK1, 6)
void radial_fused(const float4* __restrict__ x4,
                  const float4* __restrict__ y4,
                  const float4* __restrict__ d4,
                  int nvec,
                  const float* __restrict__ x,
                  const float* __restrict__ y,
                  const float* __restrict__ dist,
                  int n,
                  float* __restrict__ out)
{
    float sm[4] = {0.f, 0.f, 0.f, 0.f};   // combined sums per bin
    unsigned cntp = 0u;                    // 4 packed 8-bit counts

    const int stride = gridDim.x * blockDim.x;
    #pragma unroll 2
    for (int i = blockIdx.x * blockDim.x + threadIdx.x; i < nvec; i += stride) {
        float4 dd = __ldcs(d4 + i);
        float4 xa = __ldcs(x4 + 2 * i + 0);
        float4 xb = __ldcs(x4 + 2 * i + 1);
        float4 ya = __ldcs(y4 + 2 * i + 0);
        float4 yb = __ldcs(y4 + 2 * i + 1);

        float ds[4] = {dd.x, dd.y, dd.z, dd.w};
        float e0[4] = {xa.x, xa.z, xb.x, xb.z};
        float e1[4] = {xa.y, xa.w, xb.y, xb.w};
        float f0[4] = {ya.x, ya.z, yb.x, yb.z};
        float f1[4] = {ya.y, ya.w, yb.y, yb.w};

        #pragma unroll
        for (int e = 0; e < 4; e++) {
            float a = e0[e], b = e1[e], c = f0[e], d = f1[e];
            float u  = a - c;
            float v  = b - d;
            float d2 = fmaf(u, u, v * v);
            // (|x|-|y|)^2 = x2 + y2 - 2*sqrt(x2*y2)  -- one MUFU per element
            float x2 = fmaf(a, a, b * b);
            float y2 = fmaf(c, c, d * d);
            float p  = fmaxf(x2 * y2, 1e-30f);
            float s  = p * rsqrtf(p);               // ~sqrt(x2*y2)
            float a2 = x2 + y2 - 2.0f * s;
            float m  = fmaf(0.2f, a2, d2);          // d2 + 0.2*(|x|-|y|)^2
            int ib = (int)(ds[e] * 4.0f);
            ib = ib > 3 ? 3 : ib;
            cntp += 1u << (ib << 3);
            #pragma unroll
            for (int bb = 0; bb < 4; bb++)
                if (bb == ib) sm[bb] += m;
        }
    }

    // Scalar tail (n % 4 != 0) — no-op for this problem size, kept for safety.
    if (blockIdx.x == 0 && threadIdx.x == 0) {
        for (int j = nvec * 4; j < n; j++) {
            float a = x[2 * j], b = x[2 * j + 1];
            float c = y[2 * j], d = y[2 * j + 1];
            float u  = a - c, v = b - d;
            float d2 = fmaf(u, u, v * v);
            float x2 = fmaf(a, a, b * b);
            float y2 = fmaf(c, c, d * d);
            float p  = fmaxf(x2 * y2, 1e-30f);
            float s  = p * rsqrtf(p);
            float a2 = x2 + y2 - 2.0f * s;
            float m  = fmaf(0.2f, a2, d2);
            int ib = (int)(dist[j] * 4.0f);
            ib = ib > 3 ? 3 : ib;
            sm[ib] += m;
            cntp += 1u << (ib << 3);
        }
    }

    // Unpack counts; block-reduce 8 values in fixed order (deterministic).
    float v[8];
    #pragma unroll
    for (int b = 0; b < 4; b++) {
        v[b]     = sm[b];
        v[4 + b] = (float)((cntp >> (b << 3)) & 0xFFu);
    }

    __shared__ float sh[BLOCK1 / 32][8];
    const int lane = threadIdx.x & 31;
    const int wid  = threadIdx.x >> 5;

    #pragma unroll
    for (int k = 0; k < 8; k++) {
        #pragma unroll
        for (int o = 16; o > 0; o >>= 1)
            v[k] += __shfl_down_sync(0xffffffffu, v[k], o);
    }
    if (lane == 0) {
        #pragma unroll
        for (int k = 0; k < 8; k++) sh[wid][k] = v[k];
    }
    __syncthreads();
    if (threadIdx.x < 8) {
        float s = 0.f;
        #pragma unroll
        for (int w = 0; w < BLOCK1 / 32; w++) s += sh[w][threadIdx.x];
        g_partials[blockIdx.x * 8 + threadIdx.x] = s;
    }

    // ---- last-block final reduction (threadfence + ticket) ----
    __shared__ int isLast;
    __threadfence();
    if (threadIdx.x == 0) {
        unsigned t = atomicAdd(&g_ticket, 1u);
        isLast = (t == (unsigned)(gridDim.x - 1));
    }
    __syncthreads();
    if (!isLast) return;

    const int k  = threadIdx.x & 7;
    const int r0 = threadIdx.x >> 3;
    float acc = 0.f;
    for (int r = r0; r < GRID1; r += 32)          // fixed order per thread
        acc += g_partials[r * 8 + k];

    __shared__ float sh2[256];
    __shared__ float fin[8];
    sh2[threadIdx.x] = acc;
    __syncthreads();
    if (threadIdx.x < 8) {
        float s = 0.f;
        #pragma unroll
        for (int j = 0; j < 32; j++) s += sh2[j * 8 + threadIdx.x];
        fin[threadIdx.x] = s;
    }
    __syncthreads();

    if (threadIdx.x == 0) {
        float loss = 0.f;
        #pragma unroll
        for (int b = 0; b < 4; b++) {
            float c = fin[4 + b];
            if (c > 0.f) loss += fin[b] / (2.0f * c);
        }
        out[0] = loss;
        g_ticket = 0u;   // reset for next graph replay
    }
}

extern "C" void kernel_launch(void* const* d_in, const int* in_sizes, int n_in,
                              void* d_out, int out_size)
{
    const float* x    = (const float*)d_in[0];   // [N,2] f32
    const float* y    = (const float*)d_in[1];   // [N,2] f32
    const float* dist = (const float*)d_in[2];   // [N]   f32
    const int n    = in_sizes[2];
    const int nvec = n >> 2;

    radial_fused<<<GRID1, BLOCK1>>>(
        (const float4*)x, (const float4*)y, (const float4*)dist,
        nvec, x, y, dist, n, (float*)d_out);
}

// round 4
// speedup vs baseline: 1.1716x; 1.0689x over previous
#include <cuda_runtime.h>

#define GRID1  592          // 148 SMs * 4 CTAs -> exactly one resident wave
#define BLOCK1 256

__device__ float        g_partials[GRID1 * 8];
__device__ unsigned int g_ticket;   // zero-init; last block resets each launch

struct Acc {
    float sm[4];
    unsigned cntp;
};

__device__ __forceinline__ void process4(Acc& A, const float4& dd,
                                         const float4& xa, const float4& xb,
                                         const float4& ya, const float4& yb)
{
    float ds[4] = {dd.x, dd.y, dd.z, dd.w};
    float e0[4] = {xa.x, xa.z, xb.x, xb.z};
    float e1[4] = {xa.y, xa.w, xb.y, xb.w};
    float f0[4] = {ya.x, ya.z, yb.x, yb.z};
    float f1[4] = {ya.y, ya.w, yb.y, yb.w};

    #pragma unroll
    for (int e = 0; e < 4; e++) {
        float a = e0[e], b = e1[e], c = f0[e], d = f1[e];
        float u  = a - c;
        float v  = b - d;
        float d2 = fmaf(u, u, v * v);
        // (|x|-|y|)^2 = x2 + y2 - 2*sqrt(x2*y2): one MUFU per element
        float x2 = fmaf(a, a, b * b);
        float y2 = fmaf(c, c, d * d);
        float p  = fmaxf(x2 * y2, 1e-30f);
        float s  = p * rsqrtf(p);
        float a2 = x2 + y2 - 2.0f * s;
        float m  = fmaf(0.2f, a2, d2);
        int ib = (int)(ds[e] * 4.0f);
        ib = ib > 3 ? 3 : ib;
        A.cntp += 1u << (ib << 3);
        #pragma unroll
        for (int bb = 0; bb < 4; bb++)
            if (bb == ib) A.sm[bb] += m;
    }
}

__global__ __launch_bounds__(BLOCK1, 4)
void radial_fused(const float4* __restrict__ x4,
                  const float4* __restrict__ y4,
                  const float4* __restrict__ d4,
                  int nvec,
                  const float* __restrict__ x,
                  const float* __restrict__ y,
                  const float* __restrict__ dist,
                  int n,
                  float* __restrict__ out)
{
    Acc A;
    A.sm[0] = A.sm[1] = A.sm[2] = A.sm[3] = 0.f;
    A.cntp = 0u;

    const int stride = gridDim.x * blockDim.x;
    int i = blockIdx.x * blockDim.x + threadIdx.x;

    // Pair-batched main loop: issue 10 independent LDG.128 before consuming.
    for (; i + stride < nvec; i += 2 * stride) {
        const int j = i + stride;
        float4 dA  = __ldcs(d4 + i);
        float4 dB  = __ldcs(d4 + j);
        float4 xa0 = __ldcs(x4 + 2 * i + 0);
        float4 xa1 = __ldcs(x4 + 2 * i + 1);
        float4 xb0 = __ldcs(x4 + 2 * j + 0);
        float4 xb1 = __ldcs(x4 + 2 * j + 1);
        float4 ya0 = __ldcs(y4 + 2 * i + 0);
        float4 ya1 = __ldcs(y4 + 2 * i + 1);
        float4 yb0 = __ldcs(y4 + 2 * j + 0);
        float4 yb1 = __ldcs(y4 + 2 * j + 1);

        process4(A, dA, xa0, xa1, ya0, ya1);
        process4(A, dB, xb0, xb1, yb0, yb1);
    }
    // Epilogue: at most one more vector group per thread.
    for (; i < nvec; i += stride) {
        float4 dA  = __ldcs(d4 + i);
        float4 xa0 = __ldcs(x4 + 2 * i + 0);
        float4 xa1 = __ldcs(x4 + 2 * i + 1);
        float4 ya0 = __ldcs(y4 + 2 * i + 0);
        float4 ya1 = __ldcs(y4 + 2 * i + 1);
        process4(A, dA, xa0, xa1, ya0, ya1);
    }

    // Scalar tail (n % 4 != 0) — no-op at this problem size.
    if (blockIdx.x == 0 && threadIdx.x == 0) {
        for (int jj = nvec * 4; jj < n; jj++) {
            float a = x[2 * jj], b = x[2 * jj + 1];
            float c = y[2 * jj], d = y[2 * jj + 1];
            float u  = a - c, v = b - d;
            float d2 = fmaf(u, u, v * v);
            float x2 = fmaf(a, a, b * b);
            float y2 = fmaf(c, c, d * d);
            float p  = fmaxf(x2 * y2, 1e-30f);
            float s  = p * rsqrtf(p);
            float a2 = x2 + y2 - 2.0f * s;
            float m  = fmaf(0.2f, a2, d2);
            int ib = (int)(dist[jj] * 4.0f);
            ib = ib > 3 ? 3 : ib;
            A.sm[ib] += m;
            A.cntp += 1u << (ib << 3);
        }
    }

    // Block reduction of 8 values in fixed order (deterministic).
    float v[8];
    #pragma unroll
    for (int b = 0; b < 4; b++) {
        v[b]     = A.sm[b];
        v[4 + b] = (float)((A.cntp >> (b << 3)) & 0xFFu);
    }

    __shared__ float sh[BLOCK1 / 32][8];
    const int lane = threadIdx.x & 31;
    const int wid  = threadIdx.x >> 5;

    #pragma unroll
    for (int k = 0; k < 8; k++) {
        #pragma unroll
        for (int o = 16; o > 0; o >>= 1)
            v[k] += __shfl_down_sync(0xffffffffu, v[k], o);
    }
    if (lane == 0) {
        #pragma unroll
        for (int k = 0; k < 8; k++) sh[wid][k] = v[k];
    }
    __syncthreads();
    if (threadIdx.x < 8) {
        float s = 0.f;
        #pragma unroll
        for (int w = 0; w < BLOCK1 / 32; w++) s += sh[w][threadIdx.x];
        g_partials[blockIdx.x * 8 + threadIdx.x] = s;
    }

    // ---- last-block final reduction (threadfence + ticket) ----
    __shared__ int isLast;
    __threadfence();
    if (threadIdx.x == 0) {
        unsigned t = atomicAdd(&g_ticket, 1u);
        isLast = (t == (unsigned)(gridDim.x - 1));
    }
    __syncthreads();
    if (!isLast) return;

    const int k  = threadIdx.x & 7;
    const int r0 = threadIdx.x >> 3;
    float acc = 0.f;
    for (int r = r0; r < GRID1; r += 32)          // fixed order per thread
        acc += g_partials[r * 8 + k];

    __shared__ float sh2[256];
    __shared__ float fin[8];
    sh2[threadIdx.x] = acc;
    __syncthreads();
    if (threadIdx.x < 8) {
        float s = 0.f;
        #pragma unroll
        for (int jj = 0; jj < 32; jj++) s += sh2[jj * 8 + threadIdx.x];
        fin[threadIdx.x] = s;
    }
    __syncthreads();

    if (threadIdx.x == 0) {
        float loss = 0.f;
        #pragma unroll
        for (int b = 0; b < 4; b++) {
            float c = fin[4 + b];
            if (c > 0.f) loss += fin[b] / (2.0f * c);
        }
        out[0] = loss;
        g_ticket = 0u;   // reset for next graph replay
    }
}

extern "C" void kernel_launch(void* const* d_in, const int* in_sizes, int n_in,
                              void* d_out, int out_size)
{
    const float* x    = (const float*)d_in[0];   // [N,2] f32
    const float* y    = (const float*)d_in[1];   // [N,2] f32
    const float* dist = (const float*)d_in[2];   // [N]   f32
    const int n    = in_sizes[2];
    const int nvec = n >> 2;

    radial_fused<<<GRID1, BLOCK1>>>(
        (const float4*)x, (const float4*)y, (const float4*)dist,
        nvec, x, y, dist, n, (float*)d_out);
}